// round 6
// baseline (speedup 1.0000x reference)
#include <cuda_runtime.h>

#define BB   256
#define TT   1024
#define SS   7
#define HH   64
#define LL   4
#define OO   3
#define BETA 0.8f
#define TH   1.0f

typedef unsigned long long u64;

// Packed f32x2 FMA: one issue, two fp32 FMAs (Blackwell; only reachable via PTX).
__device__ __forceinline__ u64 ffma2(u64 a, u64 b, u64 c) {
    u64 d;
    asm("fma.rn.f32x2 %0, %1, %2, %3;" : "=l"(d) : "l"(a), "l"(b), "l"(c));
    return d;
}
__device__ __forceinline__ float2 unpack2(u64 v) {
    float2 f;
    asm("mov.b64 {%0, %1}, %2;" : "=f"(f.x), "=f"(f.y) : "l"(v));
    return f;
}

// One CTA per batch element. Threads 0..255: (layer l = tid>>6, unit h = tid&63),
// each owns membrane m[l][h] and its 64-float weight row packed as 32 f32x2
// registers. Threads 256..258: output-layer dot products. Layers pipelined
// across timesteps; double-buffered SMEM spike vectors; one __syncthreads/stage.
// Packed-lane accumulation order reproduces the scalar a0/a1/a2/a3 partial sums
// exactly (lane k accumulates indices ≡ k (mod 4)), so results are bit-identical
// to the R1 passing kernel.
__global__ __launch_bounds__(288, 2)
void snn_pipeline_kernel(const float* __restrict__ x,
                         const float* __restrict__ hidden0,
                         const float* __restrict__ w1,
                         const float* __restrict__ b1,
                         const float* __restrict__ w_h,
                         const float* __restrict__ b_h,
                         const float* __restrict__ w_out,
                         const float* __restrict__ b_out,
                         float* __restrict__ out_outputs,   // [B,T,OO]
                         float* __restrict__ out_hidden,    // [B,T,LL,HH]
                         float* __restrict__ out_xcopy)     // [B,T,SS]
{
    const int b   = blockIdx.x;
    const int tid = threadIdx.x;

    __shared__ __align__(16) float spk[2][LL][HH];   // double-buffered spikes

    // ---- copy this batch's x slice to the output buffer (coalesced float4) ----
    {
        const float4* xs4 = (const float4*)(x + (size_t)b * TT * SS);
        float4*       xo4 = (float4*)(out_xcopy + (size_t)b * TT * SS);
        const int n4 = TT * SS / 4;  // 1792
        for (int i = tid; i < n4; i += blockDim.x) xo4[i] = xs4[i];
    }

    const int  l        = tid >> 6;
    const int  h        = tid & 63;
    const bool is_layer = (tid < LL * HH);
    const bool is_out   = (tid >= LL * HH) && (tid < LL * HH + OO);

    u64   wp[HH / 2];        // packed weight row (layers 1..3 / out)
    float w0[SS];            // layer-0 row (7 floats)
    float bias = 0.0f;
    float m    = 0.0f;

    if (is_layer) {
        m = hidden0[(size_t)b * TT * LL * HH + (size_t)l * HH + h];
        if (l == 0) {
            #pragma unroll
            for (int k = 0; k < SS; k++) w0[k] = w1[h * SS + k];
            bias = b1[h];
        } else {
            const u64* wr = (const u64*)(w_h + ((size_t)(l - 1) * HH + h) * HH);
            #pragma unroll
            for (int i = 0; i < HH / 2; i++) wp[i] = wr[i];
            bias = b_h[(l - 1) * HH + h];
        }
    } else if (is_out) {
        const int j = tid - LL * HH;
        const u64* wr = (const u64*)(w_out + (size_t)j * HH);
        #pragma unroll
        for (int i = 0; i < HH / 2; i++) wp[i] = wr[i];
        bias = b_out[j];
    }

    __syncthreads();

    // per-thread streaming pointers (incremented each stage, no re-indexing)
    const float* xrow   = x + (size_t)b * TT * SS;                      // layer 0
    float*       hidptr = out_hidden + (size_t)b * TT * LL * HH + l * HH + h;
    float*       outptr = out_outputs + (size_t)b * TT * OO + (tid - LL * HH);

    const float (*rd)[HH] = spk[1];   // read buffer (written last stage)
    float       (*wr)[HH] = spk[0];   // write buffer (this stage)

    for (int s = 0; s < TT + LL; s++) {
        if (is_layer) {
            const int t = s - l;
            if (t >= 0 && t < TT) {
                float c;
                if (l == 0) {
                    c = bias;
                    #pragma unroll
                    for (int k = 0; k < SS; k++) c = fmaf(xrow[k], w0[k], c);
                    xrow += SS;
                } else {
                    const ulonglong2* sp2 = (const ulonglong2*)rd[l - 1];
                    u64 acc0 = 0ull, acc1 = 0ull;
                    #pragma unroll
                    for (int i = 0; i < HH / 4; i++) {
                        ulonglong2 sv = sp2[i];
                        acc0 = ffma2(sv.x, wp[2 * i + 0], acc0);
                        acc1 = ffma2(sv.y, wp[2 * i + 1], acc1);
                    }
                    float2 f0 = unpack2(acc0), f1 = unpack2(acc1);
                    c = bias + ((f0.x + f0.y) + (f1.x + f1.y));
                }
                const float reset = (m > TH) ? TH : 0.0f;
                const float m_new = fmaf(BETA, m, c) - reset;
                m = m_new;
                wr[l][h] = (m_new > TH) ? 1.0f : 0.0f;
                *hidptr = m_new;
                hidptr += LL * HH;
            }
        } else if (is_out) {
            const int t = s - LL;  // layer-3 spikes written at stage s-1
            if (t >= 0) {
                const ulonglong2* sp2 = (const ulonglong2*)rd[LL - 1];
                u64 acc0 = 0ull, acc1 = 0ull;
                #pragma unroll
                for (int i = 0; i < HH / 4; i++) {
                    ulonglong2 sv = sp2[i];
                    acc0 = ffma2(sv.x, wp[2 * i + 0], acc0);
                    acc1 = ffma2(sv.y, wp[2 * i + 1], acc1);
                }
                float2 f0 = unpack2(acc0), f1 = unpack2(acc1);
                *outptr = bias + ((f0.x + f0.y) + (f1.x + f1.y));
                outptr += OO;
            }
        }
        __syncthreads();
        // swap double buffers
        const float (*tmp)[HH] = rd; rd = (const float (*)[HH])wr; wr = (float (*)[HH])tmp;
    }
}

extern "C" void kernel_launch(void* const* d_in, const int* in_sizes, int n_in,
                              void* d_out, int out_size) {
    // metadata order: x, hidden_states, prev_obs, w1, b1, w_h, b_h, w_out, b_out
    const float* x       = (const float*)d_in[0];
    const float* hidden0 = (const float*)d_in[1];
    // d_in[2] = prev_obs (unused by reference)
    const float* w1      = (const float*)d_in[3];
    const float* b1      = (const float*)d_in[4];
    const float* w_h     = (const float*)d_in[5];
    const float* b_h     = (const float*)d_in[6];
    const float* w_out   = (const float*)d_in[7];
    const float* b_out   = (const float*)d_in[8];

    float* out_outputs = (float*)d_out;                                  // B*T*OO
    float* out_hidden  = out_outputs + (size_t)BB * TT * OO;             // B*T*LL*HH
    float* out_xcopy   = out_hidden + (size_t)BB * TT * LL * HH;         // B*T*SS

    snn_pipeline_kernel<<<BB, 288>>>(x, hidden0, w1, b1, w_h, b_h, w_out, b_out,
                                     out_outputs, out_hidden, out_xcopy);
}

// round 7
// speedup vs baseline: 1.1631x; 1.1631x over previous
#include <cuda_runtime.h>

#define BB   256
#define TT   1024
#define SS   7
#define HH   64
#define LL   4
#define OO   3
#define UU   4          // timesteps per barrier epoch
#define BETA 0.8f
#define TH   1.0f

// One CTA per batch element. Threads 0..255: (layer l = tid>>6, unit h = tid&63),
// each owns membrane m[l][h] and its 64-float weight row in registers.
// Threads 256..258: output-layer dot products.
// Layers pipelined across EPOCHS of UU=4 timesteps: in epoch e, layer l
// processes t = UU*(e-l)+k, k=0..3, consuming the UU spike vectors layer l-1
// wrote in epoch e-1 (double-buffered SMEM). ONE __syncthreads per epoch
// (260 barriers instead of 1028), and the 4 matvecs per epoch are independent
// -> intra-warp ILP hides LDS/FFMA latency. Per-timestep math is bit-identical
// to the 423us R1 kernel (same 4-chain scalar-FFMA accumulation order).
__global__ __launch_bounds__(288, 2)
void snn_epoch_kernel(const float* __restrict__ x,
                      const float* __restrict__ hidden0,
                      const float* __restrict__ w1,
                      const float* __restrict__ b1,
                      const float* __restrict__ w_h,
                      const float* __restrict__ b_h,
                      const float* __restrict__ w_out,
                      const float* __restrict__ b_out,
                      float* __restrict__ out_outputs,   // [B,T,OO]
                      float* __restrict__ out_hidden,    // [B,T,LL,HH]
                      float* __restrict__ out_xcopy)     // [B,T,SS]
{
    const int b   = blockIdx.x;
    const int tid = threadIdx.x;

    __shared__ __align__(16) float spk[2][LL][UU][HH];   // double-buffered epochs

    // ---- copy this batch's x slice to the output buffer (coalesced float4) ----
    {
        const float4* xs4 = (const float4*)(x + (size_t)b * TT * SS);
        float4*       xo4 = (float4*)(out_xcopy + (size_t)b * TT * SS);
        const int n4 = TT * SS / 4;  // 1792
        for (int i = tid; i < n4; i += blockDim.x) xo4[i] = xs4[i];
    }

    const int  l        = tid >> 6;
    const int  h        = tid & 63;
    const bool is_layer = (tid < LL * HH);
    const bool is_out   = (tid >= LL * HH) && (tid < LL * HH + OO);

    float wrow[HH];
    float w0[SS];
    float bias = 0.0f;
    float m    = 0.0f;

    if (is_layer) {
        m = hidden0[(size_t)b * TT * LL * HH + (size_t)l * HH + h];
        if (l == 0) {
            #pragma unroll
            for (int k = 0; k < SS; k++) w0[k] = w1[h * SS + k];
            bias = b1[h];
        } else {
            #pragma unroll
            for (int i = 0; i < HH; i++) wrow[i] = w_h[((size_t)(l - 1) * HH + h) * HH + i];
            bias = b_h[(l - 1) * HH + h];
        }
    } else if (is_out) {
        const int j = tid - LL * HH;
        #pragma unroll
        for (int i = 0; i < HH; i++) wrow[i] = w_out[j * HH + i];
        bias = b_out[j];
    }

    __syncthreads();

    // streaming pointers
    const float* xrow   = x + (size_t)b * TT * SS;
    float*       hidptr = out_hidden + (size_t)b * TT * LL * HH + l * HH + h;
    float*       outptr = out_outputs + (size_t)b * TT * OO + (tid - LL * HH);

    const int EPOCHS = TT / UU + LL;   // 260
    int buf = 0;

    for (int e = 0; e < EPOCHS; e++) {
        if (is_layer) {
            if (e >= l && e < l + TT / UU) {
                float c[UU];
                if (l == 0) {
                    // 4 consecutive timesteps: 28 contiguous floats of x
                    #pragma unroll
                    for (int k = 0; k < UU; k++) {
                        float acc = bias;
                        #pragma unroll
                        for (int j = 0; j < SS; j++)
                            acc = fmaf(xrow[k * SS + j], w0[j], acc);
                        c[k] = acc;
                    }
                    xrow += UU * SS;
                } else {
                    // 4 independent dot products over last epoch's spikes
                    #pragma unroll
                    for (int k = 0; k < UU; k++) {
                        const float* sp = spk[buf ^ 1][l - 1][k];
                        float a0 = 0.f, a1 = 0.f, a2 = 0.f, a3 = 0.f;
                        #pragma unroll
                        for (int i = 0; i < HH; i += 4) {
                            float4 sv = *(const float4*)(sp + i);
                            a0 = fmaf(sv.x, wrow[i + 0], a0);
                            a1 = fmaf(sv.y, wrow[i + 1], a1);
                            a2 = fmaf(sv.z, wrow[i + 2], a2);
                            a3 = fmaf(sv.w, wrow[i + 3], a3);
                        }
                        c[k] = bias + ((a0 + a1) + (a2 + a3));
                    }
                }
                // sequential membrane chain over the 4 timesteps (cheap)
                #pragma unroll
                for (int k = 0; k < UU; k++) {
                    const float reset = (m > TH) ? TH : 0.0f;
                    const float m_new = fmaf(BETA, m, c[k]) - reset;
                    m = m_new;
                    spk[buf][l][k][h] = (m_new > TH) ? 1.0f : 0.0f;
                    hidptr[(size_t)k * (LL * HH)] = m_new;
                }
                hidptr += (size_t)UU * LL * HH;
            }
        } else if (is_out) {
            if (e >= LL) {
                #pragma unroll
                for (int k = 0; k < UU; k++) {
                    const float* sp = spk[buf ^ 1][LL - 1][k];
                    float a0 = 0.f, a1 = 0.f, a2 = 0.f, a3 = 0.f;
                    #pragma unroll
                    for (int i = 0; i < HH; i += 4) {
                        float4 sv = *(const float4*)(sp + i);
                        a0 = fmaf(sv.x, wrow[i + 0], a0);
                        a1 = fmaf(sv.y, wrow[i + 1], a1);
                        a2 = fmaf(sv.z, wrow[i + 2], a2);
                        a3 = fmaf(sv.w, wrow[i + 3], a3);
                    }
                    outptr[k * OO] = bias + ((a0 + a1) + (a2 + a3));
                }
                outptr += UU * OO;
            }
        }
        __syncthreads();
        buf ^= 1;
    }
}

extern "C" void kernel_launch(void* const* d_in, const int* in_sizes, int n_in,
                              void* d_out, int out_size) {
    // metadata order: x, hidden_states, prev_obs, w1, b1, w_h, b_h, w_out, b_out
    const float* x       = (const float*)d_in[0];
    const float* hidden0 = (const float*)d_in[1];
    // d_in[2] = prev_obs (unused by reference)
    const float* w1      = (const float*)d_in[3];
    const float* b1      = (const float*)d_in[4];
    const float* w_h     = (const float*)d_in[5];
    const float* b_h     = (const float*)d_in[6];
    const float* w_out   = (const float*)d_in[7];
    const float* b_out   = (const float*)d_in[8];

    float* out_outputs = (float*)d_out;                                  // B*T*OO
    float* out_hidden  = out_outputs + (size_t)BB * TT * OO;             // B*T*LL*HH
    float* out_xcopy   = out_hidden + (size_t)BB * TT * LL * HH;         // B*T*SS

    snn_epoch_kernel<<<BB, 288>>>(x, hidden0, w1, b1, w_h, b_h, w_out, b_out,
                                  out_outputs, out_hidden, out_xcopy);
}